// round 1
// baseline (speedup 1.0000x reference)
#include <cuda_runtime.h>
#include <math.h>

#define NN 16000
#define EE 256000
#define DIN 256
#define HH 8
#define DD 32
#define HD 256

#define EOUT_OFF  (NN * HD)             // 4,096,000
#define COORD_OFF (NN * HD + EE * HD)   // 69,632,000

// ---- scratch (static device globals; no runtime allocation) ----
__device__ float g_q[NN * HD];
__device__ float g_k[NN * HD];
__device__ float g_v[NN * HD];
__device__ float g_wV[NN * HD];
__device__ float g_z[NN * HH];
__device__ int   g_row[EE];
__device__ int   g_col[EE];
__device__ int   g_is64;

// ---------------------------------------------------------------------------
// Detect whether edge_index is int64 or int32. If the buffer is int64, every
// entry interpreted as int64 lies in [0, NN). If it is int32, interpreting
// pairs as int64 yields v_lo + v_hi*2^32 which is >= NN with overwhelming
// probability for random indices. We check 512 entries (4 KB, always in
// bounds for either dtype).
// ---------------------------------------------------------------------------
__global__ void detect_kernel(const void* ei) {
    const long long* p = (const long long*)ei;
    int bad = 0;
    for (int i = threadIdx.x; i < 512; i += 32) {
        long long v = p[i];
        if (v < 0 || v >= NN) bad = 1;
    }
    bad = __any_sync(0xffffffffu, bad);
    if (threadIdx.x == 0) g_is64 = bad ? 0 : 1;
}

// Convert indices to int32 scratch and zero the accumulators.
__global__ void convert_zero_kernel(const void* ei) {
    int i = blockIdx.x * blockDim.x + threadIdx.x;
    if (i < EE) {
        if (g_is64) {
            const long long* p = (const long long*)ei;
            g_row[i] = (int)p[i];
            g_col[i] = (int)p[EE + i];
        } else {
            const int* p = (const int*)ei;
            g_row[i] = p[i];
            g_col[i] = p[EE + i];
        }
    }
    if (i < NN * HD) g_wV[i] = 0.0f;
    if (i < NN * HH) g_z[i]  = 0.0f;
}

// ---------------------------------------------------------------------------
// q/k/v GEMM: [16000,256] @ [256,256] x3 (blockIdx.y selects W / output).
// Block tile 128x256, thread tile 8x16 (256 threads).
// ---------------------------------------------------------------------------
__global__ __launch_bounds__(256, 1) void qkv_kernel(
    const float* __restrict__ x,
    const float* __restrict__ Wq,
    const float* __restrict__ Wk,
    const float* __restrict__ Wv)
{
    __shared__ float As[16][128];
    __shared__ float Bs[16][256];

    const float* W    = (blockIdx.y == 0) ? Wq  : (blockIdx.y == 1) ? Wk  : Wv;
    float*       outp = (blockIdx.y == 0) ? g_q : (blockIdx.y == 1) ? g_k : g_v;

    int tid = threadIdx.x;
    int tx = tid & 15;   // column group: cols {tx, tx+16, ..., tx+240}
    int ty = tid >> 4;   // row group: rows [ty*8, ty*8+8)
    int m0 = blockIdx.x * 128;

    float acc[8][16];
    #pragma unroll
    for (int i = 0; i < 8; i++)
        #pragma unroll
        for (int j = 0; j < 16; j++) acc[i][j] = 0.0f;

    for (int k0 = 0; k0 < DIN; k0 += 16) {
        __syncthreads();
        #pragma unroll
        for (int r = 0; r < 2; r++) {          // A: 128x16 -> As[k][m]
            int idx4 = tid + r * 256;
            int m  = idx4 >> 2;
            int k4 = idx4 & 3;
            float4 a = *(const float4*)&x[(size_t)(m0 + m) * DIN + k0 + k4 * 4];
            As[k4*4+0][m] = a.x; As[k4*4+1][m] = a.y;
            As[k4*4+2][m] = a.z; As[k4*4+3][m] = a.w;
        }
        #pragma unroll
        for (int r = 0; r < 4; r++) {          // B: 16x256 -> Bs[k][c]
            int idx4 = tid + r * 256;
            int k  = idx4 >> 6;
            int c4 = idx4 & 63;
            *(float4*)&Bs[k][c4*4] = *(const float4*)&W[(size_t)(k0 + k) * HD + c4 * 4];
        }
        __syncthreads();
        #pragma unroll
        for (int kk = 0; kk < 16; kk++) {
            float a[8], b[16];
            #pragma unroll
            for (int i = 0; i < 8; i++)  a[i] = As[kk][ty*8 + i];
            #pragma unroll
            for (int j = 0; j < 16; j++) b[j] = Bs[kk][tx + j*16];
            #pragma unroll
            for (int i = 0; i < 8; i++)
                #pragma unroll
                for (int j = 0; j < 16; j++)
                    acc[i][j] = fmaf(a[i], b[j], acc[i][j]);
        }
    }

    #pragma unroll
    for (int i = 0; i < 8; i++) {
        int m = m0 + ty*8 + i;
        #pragma unroll
        for (int j = 0; j < 16; j++)
            outp[(size_t)m * HD + tx + j*16] = acc[i][j];
    }
}

// ---------------------------------------------------------------------------
// Edge kernel: ea = [edge_attr, 0.1*dist] @ We fused with the attention
// epilogue. Block = 128 edges x 256 cols, thread tile 8x16.
// Thread tx covers cols {tx + 16j}; head h = j>>1, d = tx (+16).
// ---------------------------------------------------------------------------
__global__ __launch_bounds__(256, 1) void edge_kernel(
    const float* __restrict__ edge_attr,
    const float* __restrict__ coords,
    const float* __restrict__ We,
    float* __restrict__ out)
{
    __shared__ float As[16][128];
    __shared__ float Bs[16][256];
    __shared__ float wlast_s[256];
    __shared__ float dist_s[128];
    __shared__ int   row_s[128];
    __shared__ int   col_s[128];

    int tid = threadIdx.x;
    int tx = tid & 15;
    int ty = tid >> 4;
    int e0 = blockIdx.x * 128;

    // prologue: last We row + per-edge indices/distances
    wlast_s[tid] = We[(size_t)256 * HD + tid];
    if (tid < 128) {
        int e = e0 + tid;
        int r = g_row[e], c = g_col[e];
        row_s[tid] = r; col_s[tid] = c;
        float dx = coords[r*3+0] - coords[c*3+0];
        float dy = coords[r*3+1] - coords[c*3+1];
        float dz = coords[r*3+2] - coords[c*3+2];
        dist_s[tid] = 0.1f * sqrtf(dx*dx + dy*dy + dz*dz);
    }

    float acc[8][16];
    #pragma unroll
    for (int i = 0; i < 8; i++)
        #pragma unroll
        for (int j = 0; j < 16; j++) acc[i][j] = 0.0f;

    for (int k0 = 0; k0 < DIN; k0 += 16) {
        __syncthreads();
        #pragma unroll
        for (int r = 0; r < 2; r++) {
            int idx4 = tid + r * 256;
            int m  = idx4 >> 2;
            int k4 = idx4 & 3;
            float4 a = *(const float4*)&edge_attr[(size_t)(e0 + m) * DIN + k0 + k4 * 4];
            As[k4*4+0][m] = a.x; As[k4*4+1][m] = a.y;
            As[k4*4+2][m] = a.z; As[k4*4+3][m] = a.w;
        }
        #pragma unroll
        for (int r = 0; r < 4; r++) {
            int idx4 = tid + r * 256;
            int k  = idx4 >> 6;
            int c4 = idx4 & 63;
            *(float4*)&Bs[k][c4*4] = *(const float4*)&We[(size_t)(k0 + k) * HD + c4 * 4];
        }
        __syncthreads();
        #pragma unroll
        for (int kk = 0; kk < 16; kk++) {
            float a[8], b[16];
            #pragma unroll
            for (int i = 0; i < 8; i++)  a[i] = As[kk][ty*8 + i];
            #pragma unroll
            for (int j = 0; j < 16; j++) b[j] = Bs[kk][tx + j*16];
            #pragma unroll
            for (int i = 0; i < 8; i++)
                #pragma unroll
                for (int j = 0; j < 16; j++)
                    acc[i][j] = fmaf(a[i], b[j], acc[i][j]);
        }
    }
    __syncthreads();

    const float inv_sqrt_d = 0.17677669529663687f;  // 1/sqrt(32)
    float* eout = out + EOUT_OFF;

    #pragma unroll 1
    for (int i = 0; i < 8; i++) {
        int m  = ty*8 + i;
        int e  = e0 + m;
        int rn = row_s[m];
        int cn = col_s[m];
        float dist = dist_s[m];

        float sp[8];
        #pragma unroll
        for (int h = 0; h < 8; h++) sp[h] = 0.0f;

        #pragma unroll
        for (int j = 0; j < 16; j++) {
            int c = tx + j*16;
            float ea = fmaf(dist, wlast_s[c], acc[i][j]);
            float qv = g_q[(size_t)cn * HD + c];
            float kv = g_k[(size_t)rn * HD + c];
            float t = kv * qv * inv_sqrt_d;
            t = fminf(5.0f, fmaxf(-5.0f, t));
            float al = t * ea;
            eout[(size_t)e * HD + c] = al;
            sp[j >> 1] += al;
        }

        // reduce over the 16 tx lanes (stays within each 16-lane half-warp)
        #pragma unroll
        for (int off = 8; off >= 1; off >>= 1) {
            #pragma unroll
            for (int h = 0; h < 8; h++)
                sp[h] += __shfl_xor_sync(0xffffffffu, sp[h], off);
        }

        #pragma unroll
        for (int h = 0; h < 8; h++) {
            float s = fminf(5.0f, fmaxf(-5.0f, sp[h]));
            float ax = expf(s);
            int c1 = h*32 + tx;
            int c2 = c1 + 16;
            atomicAdd(&g_wV[(size_t)cn * HD + c1], g_v[(size_t)rn * HD + c1] * ax);
            atomicAdd(&g_wV[(size_t)cn * HD + c2], g_v[(size_t)rn * HD + c2] * ax);
            if (tx == h)
                atomicAdd(&g_z[cn * HH + h], ax);
        }
    }
}

// ---------------------------------------------------------------------------
// Finalize: h_out = wV / (z + 1e-6); copy coords.
// ---------------------------------------------------------------------------
__global__ void finalize_kernel(const float* __restrict__ coords,
                                float* __restrict__ out)
{
    int i = blockIdx.x * blockDim.x + threadIdx.x;
    if (i < NN * HD) {
        int n = i >> 8;
        int h = (i >> 5) & 7;
        out[i] = g_wV[i] / (g_z[n * HH + h] + 1e-6f);
    }
    if (i < NN * 3) out[COORD_OFF + i] = coords[i];
}

// ---------------------------------------------------------------------------
extern "C" void kernel_launch(void* const* d_in, const int* in_sizes, int n_in,
                              void* d_out, int out_size)
{
    const float* x         = (const float*)d_in[0];
    const float* edge_attr = (const float*)d_in[1];
    const void*  ei        = d_in[2];
    const float* coords    = (const float*)d_in[3];
    const float* Wq        = (const float*)d_in[4];
    const float* Wk        = (const float*)d_in[5];
    const float* Wv        = (const float*)d_in[6];
    const float* We        = (const float*)d_in[7];
    float* out = (float*)d_out;

    detect_kernel<<<1, 32>>>(ei);
    convert_zero_kernel<<<(NN * HD + 255) / 256, 256>>>(ei);

    dim3 gqkv(NN / 128, 3);
    qkv_kernel<<<gqkv, 256>>>(x, Wq, Wk, Wv);

    edge_kernel<<<EE / 128, 256>>>(edge_attr, coords, We, out);

    finalize_kernel<<<(NN * HD + 255) / 256, 256>>>(coords, out);
}

// round 3
// speedup vs baseline: 5.5629x; 5.5629x over previous
#include <cuda_runtime.h>
#include <math.h>

#define NN 16000
#define EE 256000
#define DIN 256
#define HH 8
#define DD 32
#define HD 256

#define EOUT_OFF  (NN * HD)             // 4,096,000
#define COORD_OFF (NN * HD + EE * HD)   // 69,632,000

// ---- scratch (static device globals; no runtime allocation) ----
__device__ float g_q[NN * HD];
__device__ float g_k[NN * HD];
__device__ float g_v[NN * HD];
__device__ float g_ax[EE * HH];     // per-edge per-head exp(clip(sum alpha))
__device__ int   g_row[EE];
__device__ int   g_col[EE];
__device__ int   g_deg[NN];
__device__ int   g_off[NN + 1];
__device__ int   g_cursor[NN];
__device__ int   g_eid[EE];         // edge ids sorted by destination (col)
__device__ int   g_is64;

// ---------------------------------------------------------------------------
// Detect int64 vs int32 edge_index (see round-0 rationale).
// ---------------------------------------------------------------------------
__global__ void detect_kernel(const void* ei) {
    const long long* p = (const long long*)ei;
    int bad = 0;
    for (int i = threadIdx.x; i < 512; i += 32) {
        long long v = p[i];
        if (v < 0 || v >= NN) bad = 1;
    }
    bad = __any_sync(0xffffffffu, bad);
    if (threadIdx.x == 0) g_is64 = bad ? 0 : 1;
}

__global__ void zero_deg_kernel() {
    int i = blockIdx.x * blockDim.x + threadIdx.x;
    if (i < NN) g_deg[i] = 0;
}

// Convert indices to int32 + histogram of destinations.
__global__ void convert_hist_kernel(const void* ei) {
    int i = blockIdx.x * blockDim.x + threadIdx.x;
    if (i < EE) {
        int r, c;
        if (g_is64) {
            const long long* p = (const long long*)ei;
            r = (int)p[i]; c = (int)p[EE + i];
        } else {
            const int* p = (const int*)ei;
            r = p[i]; c = p[EE + i];
        }
        g_row[i] = r; g_col[i] = c;
        atomicAdd(&g_deg[c], 1);
    }
}

// Exclusive scan over g_deg (16000) -> g_off, g_cursor. Single block.
__global__ void scan_kernel() {
    __shared__ int s[1024];
    int t = threadIdx.x;
    const int PER = 16;                    // 1024*16 = 16384 >= NN
    int base = t * PER;
    int local = 0;
    int d[PER];
    #pragma unroll
    for (int i = 0; i < PER; i++) {
        int idx = base + i;
        d[i] = (idx < NN) ? g_deg[idx] : 0;
        local += d[i];
    }
    s[t] = local;
    __syncthreads();
    for (int off = 1; off < 1024; off <<= 1) {
        int v = (t >= off) ? s[t - off] : 0;
        __syncthreads();
        s[t] += v;
        __syncthreads();
    }
    int run = s[t] - local;                // exclusive prefix of this chunk
    #pragma unroll
    for (int i = 0; i < PER; i++) {
        int idx = base + i;
        if (idx < NN) { g_off[idx] = run; g_cursor[idx] = run; }
        run += d[i];
    }
    if (t == 1023) g_off[NN] = s[1023];
}

__global__ void fill_kernel() {
    int i = blockIdx.x * blockDim.x + threadIdx.x;
    if (i < EE) {
        int c = g_col[i];
        int p = atomicAdd(&g_cursor[c], 1);
        g_eid[p] = i;
    }
}

// ---------------------------------------------------------------------------
// q/k/v GEMM: [16000,256] @ [256,256] x3. Block tile 128x256, thread 8x16.
// ---------------------------------------------------------------------------
__global__ __launch_bounds__(256, 1) void qkv_kernel(
    const float* __restrict__ x,
    const float* __restrict__ Wq,
    const float* __restrict__ Wk,
    const float* __restrict__ Wv)
{
    __shared__ float As[16][128];
    __shared__ float Bs[16][256];

    const float* W    = (blockIdx.y == 0) ? Wq  : (blockIdx.y == 1) ? Wk  : Wv;
    float*       outp = (blockIdx.y == 0) ? g_q : (blockIdx.y == 1) ? g_k : g_v;

    int tid = threadIdx.x;
    int tx = tid & 15;
    int ty = tid >> 4;
    int m0 = blockIdx.x * 128;

    float acc[8][16];
    #pragma unroll
    for (int i = 0; i < 8; i++)
        #pragma unroll
        for (int j = 0; j < 16; j++) acc[i][j] = 0.0f;

    for (int k0 = 0; k0 < DIN; k0 += 16) {
        __syncthreads();
        #pragma unroll
        for (int r = 0; r < 2; r++) {
            int idx4 = tid + r * 256;
            int m  = idx4 >> 2;
            int k4 = idx4 & 3;
            float4 a = *(const float4*)&x[(size_t)(m0 + m) * DIN + k0 + k4 * 4];
            As[k4*4+0][m] = a.x; As[k4*4+1][m] = a.y;
            As[k4*4+2][m] = a.z; As[k4*4+3][m] = a.w;
        }
        #pragma unroll
        for (int r = 0; r < 4; r++) {
            int idx4 = tid + r * 256;
            int k  = idx4 >> 6;
            int c4 = idx4 & 63;
            *(float4*)&Bs[k][c4*4] = *(const float4*)&W[(size_t)(k0 + k) * HD + c4 * 4];
        }
        __syncthreads();
        #pragma unroll
        for (int kk = 0; kk < 16; kk++) {
            float a[8], b[16];
            #pragma unroll
            for (int i = 0; i < 8; i++)  a[i] = As[kk][ty*8 + i];
            #pragma unroll
            for (int j = 0; j < 16; j++) b[j] = Bs[kk][tx + j*16];
            #pragma unroll
            for (int i = 0; i < 8; i++)
                #pragma unroll
                for (int j = 0; j < 16; j++)
                    acc[i][j] = fmaf(a[i], b[j], acc[i][j]);
        }
    }

    #pragma unroll
    for (int i = 0; i < 8; i++) {
        int m = m0 + ty*8 + i;
        #pragma unroll
        for (int j = 0; j < 16; j++)
            outp[(size_t)m * HD + tx + j*16] = acc[i][j];
    }
}

// ---------------------------------------------------------------------------
// Edge kernel: ea = [edge_attr, 0.1*dist] @ We fused with alpha / e_out /
// alphax. Block = 64 edges x 256 cols, thread tile 4x16, 16 warps/SM.
// NO atomics: per-edge alphax goes to g_ax; aggregation happens in gather.
// ---------------------------------------------------------------------------
__global__ __launch_bounds__(256, 2) void edge_kernel(
    const float* __restrict__ edge_attr,
    const float* __restrict__ coords,
    const float* __restrict__ We,
    float* __restrict__ out)
{
    __shared__ float As[16][64];
    __shared__ float Bs[16][256];
    __shared__ float wlast_s[256];
    __shared__ float dist_s[64];
    __shared__ int   row_s[64];
    __shared__ int   col_s[64];

    int tid = threadIdx.x;
    int tx = tid & 15;
    int ty = tid >> 4;
    int e0 = blockIdx.x * 64;

    wlast_s[tid] = We[(size_t)256 * HD + tid];
    if (tid < 64) {
        int e = e0 + tid;
        int r = g_row[e], c = g_col[e];
        row_s[tid] = r; col_s[tid] = c;
        float dx = coords[r*3+0] - coords[c*3+0];
        float dy = coords[r*3+1] - coords[c*3+1];
        float dz = coords[r*3+2] - coords[c*3+2];
        dist_s[tid] = 0.1f * sqrtf(dx*dx + dy*dy + dz*dz);
    }

    float acc[4][16];
    #pragma unroll
    for (int i = 0; i < 4; i++)
        #pragma unroll
        for (int j = 0; j < 16; j++) acc[i][j] = 0.0f;

    for (int k0 = 0; k0 < DIN; k0 += 16) {
        __syncthreads();
        {   // A: 64x16 -> As[k][m], one float4 per thread
            int m  = tid >> 2;
            int k4 = tid & 3;
            float4 a = *(const float4*)&edge_attr[(size_t)(e0 + m) * DIN + k0 + k4 * 4];
            As[k4*4+0][m] = a.x; As[k4*4+1][m] = a.y;
            As[k4*4+2][m] = a.z; As[k4*4+3][m] = a.w;
        }
        #pragma unroll
        for (int r = 0; r < 4; r++) {   // B: 16x256
            int idx4 = tid + r * 256;
            int k  = idx4 >> 6;
            int c4 = idx4 & 63;
            *(float4*)&Bs[k][c4*4] = *(const float4*)&We[(size_t)(k0 + k) * HD + c4 * 4];
        }
        __syncthreads();
        #pragma unroll
        for (int kk = 0; kk < 16; kk++) {
            float a[4], b[16];
            #pragma unroll
            for (int i = 0; i < 4; i++)  a[i] = As[kk][ty*4 + i];
            #pragma unroll
            for (int j = 0; j < 16; j++) b[j] = Bs[kk][tx + j*16];
            #pragma unroll
            for (int i = 0; i < 4; i++)
                #pragma unroll
                for (int j = 0; j < 16; j++)
                    acc[i][j] = fmaf(a[i], b[j], acc[i][j]);
        }
    }
    __syncthreads();

    const float inv_sqrt_d = 0.17677669529663687f;  // 1/sqrt(32)
    float* eout = out + EOUT_OFF;

    #pragma unroll 1
    for (int i = 0; i < 4; i++) {
        int m  = ty*4 + i;
        int e  = e0 + m;
        int rn = row_s[m];
        int cn = col_s[m];
        float dist = dist_s[m];

        float sp[8];
        #pragma unroll
        for (int h = 0; h < 8; h++) sp[h] = 0.0f;

        #pragma unroll
        for (int j = 0; j < 16; j++) {
            int c = tx + j*16;
            float ea = fmaf(dist, wlast_s[c], acc[i][j]);
            float qv = g_q[(size_t)cn * HD + c];
            float kv = g_k[(size_t)rn * HD + c];
            float t = kv * qv * inv_sqrt_d;
            t = fminf(5.0f, fmaxf(-5.0f, t));
            float al = t * ea;
            eout[(size_t)e * HD + c] = al;
            sp[j >> 1] += al;
        }

        // reduce over the 16 tx lanes (stays within each half-warp)
        #pragma unroll
        for (int off = 8; off >= 1; off >>= 1) {
            #pragma unroll
            for (int h = 0; h < 8; h++)
                sp[h] += __shfl_xor_sync(0xffffffffu, sp[h], off);
        }

        if (tx < 8) {
            float s = fminf(5.0f, fmaxf(-5.0f, sp[tx]));
            g_ax[(size_t)e * HH + tx] = expf(s);
        }
    }
}

// ---------------------------------------------------------------------------
// Gather + finalize: one block per destination node. No atomics.
// wV[n,c] = sum_{e in CSR(n)} v[row_e, c] * alphax[e, c/32]; out = wV/(z+eps).
// Also copies coords.
// ---------------------------------------------------------------------------
__global__ __launch_bounds__(256) void gather_kernel(
    const float* __restrict__ coords,
    float* __restrict__ out)
{
    __shared__ int se[256];
    __shared__ int sr[256];

    int n   = blockIdx.x;
    int tid = threadIdx.x;
    int h   = tid >> 5;

    int off = g_off[n];
    int end = g_off[n + 1];

    float acc  = 0.0f;
    float zacc = 0.0f;   // valid on lane 0 of each warp

    for (int base = off; base < end; base += 256) {
        int cnt = min(256, end - base);
        __syncthreads();
        for (int t = tid; t < cnt; t += 256) {
            int e = g_eid[base + t];
            se[t] = e;
            sr[t] = g_row[e];
        }
        __syncthreads();
        for (int j = 0; j < cnt; j++) {
            int e = se[j];
            int r = sr[j];
            float ax = g_ax[(size_t)e * HH + h];     // warp-uniform
            acc = fmaf(g_v[(size_t)r * HD + tid], ax, acc);
            if ((tid & 31) == 0) zacc += ax;
        }
    }

    float z = __shfl_sync(0xffffffffu, zacc, 0);
    out[(size_t)n * HD + tid] = acc / (z + 1e-6f);

    if (tid < 3) out[COORD_OFF + n*3 + tid] = coords[n*3 + tid];
}

// ---------------------------------------------------------------------------
extern "C" void kernel_launch(void* const* d_in, const int* in_sizes, int n_in,
                              void* d_out, int out_size)
{
    const float* x         = (const float*)d_in[0];
    const float* edge_attr = (const float*)d_in[1];
    const void*  ei        = d_in[2];
    const float* coords    = (const float*)d_in[3];
    const float* Wq        = (const float*)d_in[4];
    const float* Wk        = (const float*)d_in[5];
    const float* Wv        = (const float*)d_in[6];
    const float* We        = (const float*)d_in[7];
    float* out = (float*)d_out;

    detect_kernel<<<1, 32>>>(ei);
    zero_deg_kernel<<<(NN + 255) / 256, 256>>>();
    convert_hist_kernel<<<(EE + 255) / 256, 256>>>(ei);
    scan_kernel<<<1, 1024>>>();
    fill_kernel<<<(EE + 255) / 256, 256>>>();

    dim3 gqkv(NN / 128, 3);
    qkv_kernel<<<gqkv, 256>>>(x, Wq, Wk, Wv);

    edge_kernel<<<EE / 64, 256>>>(edge_attr, coords, We, out);

    gather_kernel<<<NN, 256>>>(coords, out);
}

// round 9
// speedup vs baseline: 12.6248x; 2.2694x over previous
#include <cuda_runtime.h>
#include <cuda_bf16.h>
#include <math.h>
#include <stdint.h>

#define NN 16000
#define EE 256000
#define DIN 256
#define HH 8
#define HD 256

#define EOUT_OFF  (NN * HD)             // 4,096,000
#define COORD_OFF (NN * HD + EE * HD)   // 69,632,000

// ---- scratch (static device globals; no runtime allocation) ----
__device__ float g_q[NN * HD];
__device__ float g_k[NN * HD];
__device__ float g_v[NN * HD];
__device__ float g_ax[EE * HH];
__device__ int   g_row[EE];
__device__ int   g_col[EE];
__device__ int   g_deg[NN];
__device__ int   g_off[NN + 1];
__device__ int   g_cursor[NN];
__device__ int   g_eid[EE];
__device__ int   g_is64;
// transposed (K-major, [n*256+k]) bf16 hi/lo weights: mats 0..3 = Wq,Wk,Wv,We
__device__ __nv_bfloat16 g_bt_hi[4 * 65536];
__device__ __nv_bfloat16 g_bt_lo[4 * 65536];

// ===========================================================================
// MMA helpers (sm_80-baseline HMMA — compiles for plain sm_103 target)
// ===========================================================================
__device__ __forceinline__ uint32_t smem_u32(const void* p) {
    return (uint32_t)__cvta_generic_to_shared(p);
}

#define LDSM4(r, addr)                                                        \
    asm volatile("ldmatrix.sync.aligned.m8n8.x4.shared.b16 {%0,%1,%2,%3}, [%4];" \
        : "=r"((r)[0]), "=r"((r)[1]), "=r"((r)[2]), "=r"((r)[3]) : "r"(addr))

#define MMA16816(c, a, b0, b1)                                                \
    asm volatile("mma.sync.aligned.m16n8k16.row.col.f32.bf16.bf16.f32 "       \
        "{%0,%1,%2,%3}, {%4,%5,%6,%7}, {%8,%9}, {%0,%1,%2,%3};"               \
        : "+f"((c)[0]), "+f"((c)[1]), "+f"((c)[2]), "+f"((c)[3])              \
        : "r"((a)[0]), "r"((a)[1]), "r"((a)[2]), "r"((a)[3]),                 \
          "r"(b0), "r"(b1))

// SMEM layout (byte offsets into extern shared)
// A tile: 64 rows x 64 k bf16, stride 80 elems (160B) -> 10240 B each
// B tile: 128 rows x 64 k bf16, stride 80          -> 20480 B each
#define OFF_AHI   0u
#define OFF_ALO   10240u
#define OFF_BHI   20480u
#define OFF_BLO   40960u
#define OFF_DIST  61440u
#define OFF_RN    61696u
#define OFF_CN    61952u
#define SMEM_TOT  62208u

// ===========================================================================
// Shared GEMM mainloop. Computes, per thread, acc[2][4][4] =
// fragment of D[64,128] = A[64,256] @ B[128,256]^T (bf16 hi/lo 3-pass).
// A = fp32 source rows (lda=256), split inline. B = precomputed bf16 hi/lo
// K-major rows, n offset = half*128.
// 8 warps: wm = wid&1 (32 rows), wn = wid>>1 (32 cols).
// ===========================================================================
__device__ __forceinline__ void gemm_tile(
    char* sm, uint32_t sb,
    const float* __restrict__ Asrc,
    const __nv_bfloat16* __restrict__ bhi_g,
    const __nv_bfloat16* __restrict__ blo_g,
    int half, int tid, float acc[2][4][4])
{
    const int wid = tid >> 5, lane = tid & 31;
    const int wm = wid & 1, wn = wid >> 1;
    const uint32_t lrow = lane & 15;
    const uint32_t lkh  = ((lane >> 4) & 1) << 3;

    for (int chunk = 0; chunk < 4; chunk++) {
        const int k0 = chunk * 64;
        __syncthreads();

        // ---- stage A: fp32 -> bf16 hi/lo --------------------------------
        #pragma unroll
        for (int s = 0; s < 4; s++) {
            int idx = tid + s * 256;
            int r = idx >> 4, qd = idx & 15;
            float4 a = *(const float4*)(Asrc + (size_t)r * 256 + k0 + qd * 4);
            __nv_bfloat16 h0 = __float2bfloat16(a.x);
            __nv_bfloat16 h1 = __float2bfloat16(a.y);
            __nv_bfloat16 h2 = __float2bfloat16(a.z);
            __nv_bfloat16 h3 = __float2bfloat16(a.w);
            __nv_bfloat16 l0 = __float2bfloat16(a.x - __bfloat162float(h0));
            __nv_bfloat16 l1 = __float2bfloat16(a.y - __bfloat162float(h1));
            __nv_bfloat16 l2 = __float2bfloat16(a.z - __bfloat162float(h2));
            __nv_bfloat16 l3 = __float2bfloat16(a.w - __bfloat162float(h3));
            uint2 hv, lv;
            hv.x = ((uint32_t)__bfloat16_as_ushort(h1) << 16) | __bfloat16_as_ushort(h0);
            hv.y = ((uint32_t)__bfloat16_as_ushort(h3) << 16) | __bfloat16_as_ushort(h2);
            lv.x = ((uint32_t)__bfloat16_as_ushort(l1) << 16) | __bfloat16_as_ushort(l0);
            lv.y = ((uint32_t)__bfloat16_as_ushort(l3) << 16) | __bfloat16_as_ushort(l2);
            *(uint2*)(sm + OFF_AHI + r * 160 + qd * 8) = hv;
            *(uint2*)(sm + OFF_ALO + r * 160 + qd * 8) = lv;
        }

        // ---- stage B: copy precomputed hi/lo ----------------------------
        #pragma unroll
        for (int s = 0; s < 4; s++) {
            int idx = tid + s * 256;
            int n = idx >> 3, gq = idx & 7;
            size_t src = (size_t)(half * 128 + n) * 256 + k0 + gq * 8;
            *(uint4*)(sm + OFF_BHI + n * 160 + gq * 16) = *(const uint4*)(bhi_g + src);
            *(uint4*)(sm + OFF_BLO + n * 160 + gq * 16) = *(const uint4*)(blo_g + src);
        }
        __syncthreads();

        // ---- compute 4 k16 steps ---------------------------------------
        #pragma unroll
        for (int ks = 0; ks < 4; ks++) {
            const uint32_t koff = (uint32_t)(ks * 16 + lkh) * 2;
            uint32_t ah[2][4], al[2][4], bh[2][4], bl[2][4];
            #pragma unroll
            for (int mi = 0; mi < 2; mi++) {
                uint32_t addr = sb + OFF_AHI + (uint32_t)(wm*32 + mi*16 + lrow) * 160 + koff;
                LDSM4(ah[mi], addr);
                LDSM4(al[mi], addr + (OFF_ALO - OFF_AHI));
            }
            #pragma unroll
            for (int gj = 0; gj < 2; gj++) {
                uint32_t addr = sb + OFF_BHI + (uint32_t)(wn*32 + gj*16 + lrow) * 160 + koff;
                LDSM4(bh[gj], addr);
                LDSM4(bl[gj], addr + (OFF_BLO - OFF_BHI));
            }
            #pragma unroll
            for (int mi = 0; mi < 2; mi++)
                #pragma unroll
                for (int ni = 0; ni < 4; ni++) {
                    int gj = ni >> 1, up = ni & 1;
                    uint32_t b0h = bh[gj][up], b1h = bh[gj][up + 2];
                    uint32_t b0l = bl[gj][up], b1l = bl[gj][up + 2];
                    MMA16816(acc[mi][ni], ah[mi], b0h, b1h);
                    MMA16816(acc[mi][ni], ah[mi], b0l, b1l);
                    MMA16816(acc[mi][ni], al[mi], b0h, b1h);
                }
        }
    }
}

// ===========================================================================
// Preprocessing kernels
// ===========================================================================
__global__ void detect_kernel(const void* ei) {
    const long long* p = (const long long*)ei;
    int bad = 0;
    for (int i = threadIdx.x; i < 512; i += 32) {
        long long v = p[i];
        if (v < 0 || v >= NN) bad = 1;
    }
    bad = __any_sync(0xffffffffu, bad);
    if (threadIdx.x == 0) g_is64 = bad ? 0 : 1;
}

__global__ void zero_deg_kernel() {
    int i = blockIdx.x * blockDim.x + threadIdx.x;
    if (i < NN) g_deg[i] = 0;
}

__global__ void convert_hist_kernel(const void* ei) {
    int i = blockIdx.x * blockDim.x + threadIdx.x;
    if (i < EE) {
        int r, c;
        if (g_is64) {
            const long long* p = (const long long*)ei;
            r = (int)p[i]; c = (int)p[EE + i];
        } else {
            const int* p = (const int*)ei;
            r = p[i]; c = p[EE + i];
        }
        g_row[i] = r; g_col[i] = c;
        atomicAdd(&g_deg[c], 1);
    }
}

__global__ void scan_kernel() {
    __shared__ int s[1024];
    int t = threadIdx.x;
    const int PER = 16;
    int base = t * PER;
    int local = 0;
    int d[PER];
    #pragma unroll
    for (int i = 0; i < PER; i++) {
        int idx = base + i;
        d[i] = (idx < NN) ? g_deg[idx] : 0;
        local += d[i];
    }
    s[t] = local;
    __syncthreads();
    for (int off = 1; off < 1024; off <<= 1) {
        int v = (t >= off) ? s[t - off] : 0;
        __syncthreads();
        s[t] += v;
        __syncthreads();
    }
    int run = s[t] - local;
    #pragma unroll
    for (int i = 0; i < PER; i++) {
        int idx = base + i;
        if (idx < NN) { g_off[idx] = run; g_cursor[idx] = run; }
        run += d[i];
    }
    if (t == 1023) g_off[NN] = s[1023];
}

__global__ void fill_kernel() {
    int i = blockIdx.x * blockDim.x + threadIdx.x;
    if (i < EE) {
        int c = g_col[i];
        int p = atomicAdd(&g_cursor[c], 1);
        g_eid[p] = i;
    }
}

// Transpose weights to K-major bf16 hi/lo. grid (256, 4)
__global__ void wtrans_kernel(const float* __restrict__ Wq, const float* __restrict__ Wk,
                              const float* __restrict__ Wv, const float* __restrict__ We) {
    int mat = blockIdx.y;
    const float* W = (mat == 0) ? Wq : (mat == 1) ? Wk : (mat == 2) ? Wv : We;
    int idx = blockIdx.x * 256 + threadIdx.x;
    int n = idx & 255;
    int k = idx >> 8;
    float v = W[(size_t)k * 256 + n];
    __nv_bfloat16 h = __float2bfloat16(v);
    __nv_bfloat16 l = __float2bfloat16(v - __bfloat162float(h));
    g_bt_hi[(size_t)mat * 65536 + (size_t)n * 256 + k] = h;
    g_bt_lo[(size_t)mat * 65536 + (size_t)n * 256 + k] = l;
}

// ===========================================================================
// q/k/v tensor-core GEMM. grid (250, 2, 3), 256 threads.
// ===========================================================================
__global__ __launch_bounds__(256, 2) void qkv_mma_kernel(const float* __restrict__ x) {
    extern __shared__ char sm[];
    uint32_t sb = smem_u32(sm);
    int tid = threadIdx.x;
    int m0   = blockIdx.x * 64;
    int half = blockIdx.y;
    int mat  = blockIdx.z;

    float acc[2][4][4] = {};
    gemm_tile(sm, sb, x + (size_t)m0 * 256,
              g_bt_hi + (size_t)mat * 65536, g_bt_lo + (size_t)mat * 65536,
              half, tid, acc);

    float* outp = (mat == 0) ? g_q : (mat == 1) ? g_k : g_v;
    int wid = tid >> 5, lane = tid & 31;
    int wm = wid & 1, wn = wid >> 1;
    int g = lane >> 2, quad = lane & 3;
    int cbase = half * 128 + wn * 32 + quad * 2;

    #pragma unroll
    for (int mi = 0; mi < 2; mi++)
        #pragma unroll
        for (int hh = 0; hh < 2; hh++) {
            int row = m0 + wm*32 + mi*16 + hh*8 + g;
            #pragma unroll
            for (int ni = 0; ni < 4; ni++)
                *(float2*)(outp + (size_t)row * 256 + cbase + ni*8) =
                    make_float2(acc[mi][ni][hh*2], acc[mi][ni][hh*2+1]);
        }
}

// ===========================================================================
// Edge GEMM + fused attention epilogue. grid (4000, 2), 256 threads.
// Warp wn covers exactly one head (32 cols) -> head sum is a quad shuffle.
// ===========================================================================
__global__ __launch_bounds__(256, 2) void edge_mma_kernel(
    const float* __restrict__ edge_attr,
    const float* __restrict__ coords,
    const float* __restrict__ We,
    float* __restrict__ out)
{
    extern __shared__ char sm[];
    uint32_t sb = smem_u32(sm);
    int tid = threadIdx.x;
    int e0   = blockIdx.x * 64;
    int half = blockIdx.y;

    if (tid < 64) {
        int e = e0 + tid;
        int r = g_row[e], c = g_col[e];
        ((int*)(sm + OFF_RN))[tid] = r;
        ((int*)(sm + OFF_CN))[tid] = c;
        float dx = coords[r*3+0] - coords[c*3+0];
        float dy = coords[r*3+1] - coords[c*3+1];
        float dz = coords[r*3+2] - coords[c*3+2];
        ((float*)(sm + OFF_DIST))[tid] = 0.1f * sqrtf(dx*dx + dy*dy + dz*dz);
    }

    float acc[2][4][4] = {};
    gemm_tile(sm, sb, edge_attr + (size_t)e0 * 256,
              g_bt_hi + (size_t)3 * 65536, g_bt_lo + (size_t)3 * 65536,
              half, tid, acc);

    int wid = tid >> 5, lane = tid & 31;
    int wm = wid & 1, wn = wid >> 1;
    int g = lane >> 2, quad = lane & 3;
    int head  = half * 4 + wn;
    int cbase = half * 128 + wn * 32 + quad * 2;

    float wl[4][2];
    #pragma unroll
    for (int ni = 0; ni < 4; ni++) {
        float2 w = *(const float2*)(We + (size_t)256 * 256 + cbase + ni*8);
        wl[ni][0] = w.x; wl[ni][1] = w.y;
    }

    const float inv_sqrt_d = 0.17677669529663687f;  // 1/sqrt(32)
    float* eout = out + EOUT_OFF;

    #pragma unroll
    for (int mi = 0; mi < 2; mi++)
        #pragma unroll
        for (int hh = 0; hh < 2; hh++) {
            int m = wm*32 + mi*16 + hh*8 + g;
            int e = e0 + m;
            int rn = ((int*)(sm + OFF_RN))[m];
            int cn = ((int*)(sm + OFF_CN))[m];
            float dist = ((float*)(sm + OFF_DIST))[m];
            float sum = 0.0f;
            #pragma unroll
            for (int ni = 0; ni < 4; ni++) {
                int c = cbase + ni*8;
                float2 q2 = *(const float2*)(g_q + (size_t)cn * 256 + c);
                float2 k2 = *(const float2*)(g_k + (size_t)rn * 256 + c);
                float ea0 = fmaf(dist, wl[ni][0], acc[mi][ni][hh*2+0]);
                float ea1 = fmaf(dist, wl[ni][1], acc[mi][ni][hh*2+1]);
                float t0 = fminf(5.0f, fmaxf(-5.0f, k2.x * q2.x * inv_sqrt_d));
                float t1 = fminf(5.0f, fmaxf(-5.0f, k2.y * q2.y * inv_sqrt_d));
                float a0 = t0 * ea0, a1 = t1 * ea1;
                *(float2*)(eout + (size_t)e * 256 + c) = make_float2(a0, a1);
                sum += a0 + a1;
            }
            sum += __shfl_xor_sync(0xffffffffu, sum, 1);
            sum += __shfl_xor_sync(0xffffffffu, sum, 2);
            if (quad == 0)
                g_ax[(size_t)e * HH + head] =
                    expf(fminf(5.0f, fmaxf(-5.0f, sum)));
        }
}

// ===========================================================================
// Gather + finalize: one block per destination node, no atomics.
// ===========================================================================
__global__ __launch_bounds__(256) void gather_kernel(
    const float* __restrict__ coords,
    float* __restrict__ out)
{
    __shared__ int se[256];
    __shared__ int sr[256];

    int n   = blockIdx.x;
    int tid = threadIdx.x;
    int h   = tid >> 5;

    int off = g_off[n];
    int end = g_off[n + 1];

    float acc  = 0.0f;
    float zacc = 0.0f;

    for (int base = off; base < end; base += 256) {
        int cnt = min(256, end - base);
        __syncthreads();
        for (int t = tid; t < cnt; t += 256) {
            int e = g_eid[base + t];
            se[t] = e;
            sr[t] = g_row[e];
        }
        __syncthreads();
        for (int j = 0; j < cnt; j++) {
            int e = se[j];
            int r = sr[j];
            float ax = g_ax[(size_t)e * HH + h];
            acc = fmaf(g_v[(size_t)r * HD + tid], ax, acc);
            if ((tid & 31) == 0) zacc += ax;
        }
    }

    float z = __shfl_sync(0xffffffffu, zacc, 0);
    out[(size_t)n * HD + tid] = acc / (z + 1e-6f);

    if (tid < 3) out[COORD_OFF + n*3 + tid] = coords[n*3 + tid];
}

// ===========================================================================
extern "C" void kernel_launch(void* const* d_in, const int* in_sizes, int n_in,
                              void* d_out, int out_size)
{
    const float* x         = (const float*)d_in[0];
    const float* edge_attr = (const float*)d_in[1];
    const void*  ei        = d_in[2];
    const float* coords    = (const float*)d_in[3];
    const float* Wq        = (const float*)d_in[4];
    const float* Wk        = (const float*)d_in[5];
    const float* Wv        = (const float*)d_in[6];
    const float* We        = (const float*)d_in[7];
    float* out = (float*)d_out;

    static int attr_done = 0;
    if (!attr_done) {
        cudaFuncSetAttribute(qkv_mma_kernel,
                             cudaFuncAttributeMaxDynamicSharedMemorySize, SMEM_TOT);
        cudaFuncSetAttribute(edge_mma_kernel,
                             cudaFuncAttributeMaxDynamicSharedMemorySize, SMEM_TOT);
        attr_done = 1;
    }

    detect_kernel<<<1, 32>>>(ei);
    zero_deg_kernel<<<(NN + 255) / 256, 256>>>();
    convert_hist_kernel<<<(EE + 255) / 256, 256>>>(ei);
    scan_kernel<<<1, 1024>>>();
    fill_kernel<<<(EE + 255) / 256, 256>>>();

    dim3 gtr(256, 4);
    wtrans_kernel<<<gtr, 256>>>(Wq, Wk, Wv, We);

    dim3 gqkv(250, 2, 3);
    qkv_mma_kernel<<<gqkv, 256, SMEM_TOT>>>(x);

    dim3 gedge(4000, 2);
    edge_mma_kernel<<<gedge, 256, SMEM_TOT>>>(edge_attr, coords, We, out);

    gather_kernel<<<NN, 256>>>(coords, out);
}